// round 5
// baseline (speedup 1.0000x reference)
#include <cuda_runtime.h>
#include <cstdint>

#define N_NODES 100000
#define N_EDGES 1600000
#define DIM     128
#define NL      3
#define NR      3
#define NC      16
#define NG      512

#define XPOOL_ELEMS ((size_t)NG * 384)
#define XS_BASE     (XPOOL_ELEMS)
#define LOSS_IDX    (XS_BASE + (size_t)N_NODES * 384)
#define ID_BASE     (LOSS_IDX + 1)

// ------------------------- device scratch -------------------------
__device__ float  g_h[(size_t)N_NODES * DIM];    // post-BN features (agg input)
__device__ float  g_h2[(size_t)N_NODES * DIM];   // raw MLP output (pre-BN)
__device__ float  g_cbn[NL * NR * NC * DIM];
__device__ double g_colsum[NL * DIM];
__device__ double g_colsumsq[NL * DIM];
__device__ double g_loss[NL * NR];
__device__ int    g_deg[N_NODES];
__device__ int    g_cursor[N_NODES];
__device__ int    g_csr[N_NODES + 1];
__device__ int    g_eid[N_EDGES];
__device__ int    g_src_sorted[N_EDGES];

// ------------------------- f32x2 packed math (per-lane IEEE fp32 fma) ----------
__device__ __forceinline__ unsigned long long pack2(float x) {
    unsigned long long r;
    asm("mov.b64 %0, {%1, %1};" : "=l"(r) : "f"(x));
    return r;
}
__device__ __forceinline__ unsigned long long ffma2(unsigned long long a,
                                                    unsigned long long b,
                                                    unsigned long long c) {
    unsigned long long d;
    asm("fma.rn.f32x2 %0, %1, %2, %3;" : "=l"(d) : "l"(a), "l"(b), "l"(c));
    return d;
}
__device__ __forceinline__ void unpack2(unsigned long long v, float& lo, float& hi) {
    asm("mov.b64 {%0, %1}, %2;" : "=f"(lo), "=f"(hi) : "l"(v));
}

// ------------------------- init -------------------------
__global__ void init_kernel() {
    int i = blockIdx.x * blockDim.x + threadIdx.x;
    if (i < N_NODES) { g_deg[i] = 0; g_cursor[i] = 0; }
    if (i < NL * DIM) { g_colsum[i] = 0.0; g_colsumsq[i] = 0.0; }
    if (i < NL * NR) g_loss[i] = 0.0;
}

// codebook normalization: one thread per code, sequential fp32
__global__ void cbnorm_kernel(const float* __restrict__ cb) {
    int c = blockIdx.x * blockDim.x + threadIdx.x;
    if (c >= NL * NR * NC) return;
    const float* src = cb + (size_t)c * DIM;
    float ss = 0.0f;
    for (int d = 0; d < DIM; d++) ss = __fadd_rn(ss, __fmul_rn(src[d], src[d]));
    float sc = __fdiv_rn(1.0f, __fsqrt_rn(__fadd_rn(ss, 1e-12f)));
    for (int d = 0; d < DIM; d++) g_cbn[(size_t)c * DIM + d] = __fmul_rn(src[d], sc);
}

__global__ void copy_x_kernel(const float* __restrict__ x) {
    int i = blockIdx.x * blockDim.x + threadIdx.x;
    if (i < N_NODES * (DIM / 4))
        *(float4*)(g_h + (size_t)i * 4) = *(const float4*)(x + (size_t)i * 4);
}

// ------------------------- CSR build (stable by edge id) -------------------------
__global__ void count_kernel(const int* __restrict__ ei) {
    int e = blockIdx.x * blockDim.x + threadIdx.x;
    if (e < N_EDGES) atomicAdd(&g_deg[__ldg(ei + N_EDGES + e)], 1);
}

__global__ void scan_kernel() {   // single block, 1024 threads
    __shared__ int wsum[32];
    __shared__ int carry;
    int tid = threadIdx.x, lane = tid & 31, wid = tid >> 5;
    if (tid == 0) carry = 0;
    __syncthreads();
    for (int base = 0; base < N_NODES; base += 1024) {
        int i = base + tid;
        int v = (i < N_NODES) ? g_deg[i] : 0;
        int incl = v;
        #pragma unroll
        for (int off = 1; off < 32; off <<= 1) {
            int t = __shfl_up_sync(0xffffffffu, incl, off);
            if (lane >= off) incl += t;
        }
        if (lane == 31) wsum[wid] = incl;
        __syncthreads();
        if (wid == 0) {
            int w = wsum[lane];
            #pragma unroll
            for (int off = 1; off < 32; off <<= 1) {
                int t = __shfl_up_sync(0xffffffffu, w, off);
                if (lane >= off) w += t;
            }
            wsum[lane] = w;
        }
        __syncthreads();
        int pre = (wid > 0) ? wsum[wid - 1] : 0;
        int excl = carry + pre + incl - v;
        if (i < N_NODES) g_csr[i] = excl;
        int btotal = wsum[31];
        __syncthreads();
        if (tid == 0) carry += btotal;
        __syncthreads();
    }
    if (threadIdx.x == 0) g_csr[N_NODES] = carry;
}

__global__ void place_kernel(const int* __restrict__ ei) {
    int e = blockIdx.x * blockDim.x + threadIdx.x;
    if (e >= N_EDGES) return;
    int dst = __ldg(ei + N_EDGES + e);
    int pos = g_csr[dst] + atomicAdd(&g_cursor[dst], 1);
    g_eid[pos] = e;
}

// warp-per-node rank-by-count: restores original edge order (eids distinct)
__global__ void rank_kernel(const int* __restrict__ ei) {
    int wid  = (blockIdx.x * blockDim.x + threadIdx.x) >> 5;
    if (wid >= N_NODES) return;
    int lane = threadIdx.x & 31;
    int s = g_csr[wid], e = g_csr[wid + 1], deg = e - s;
    for (int i = lane; i < deg; i += 32) {
        int my = g_eid[s + i];
        int rank = 0;
        for (int j = 0; j < deg; j++) rank += (g_eid[s + j] < my) ? 1 : 0;
        g_src_sorted[s + rank] = __ldg(ei + my);
    }
}

// ---------------- fused agg + MLP + BN stats (reads g_h, writes g_h2) ------------
#define BM 64
#define A_LD 132
#define MLP_SMEM ((BM * A_LD + DIM * DIM) * 4)

__global__ void mlp_kernel(const float* __restrict__ W1g, const float* __restrict__ b1g,
                           const float* __restrict__ W2g, const float* __restrict__ b2g,
                           int layer) {
    extern __shared__ float sm[];
    float* A = sm;
    float* W = sm + BM * A_LD;

    int tid  = threadIdx.x;
    int row0 = blockIdx.x * BM;

    // load W1 (independent; issue first so it overlaps the aggregation)
    {
        const float* Wg = W1g + (size_t)layer * DIM * DIM;
        for (int t = tid; t < 4096; t += 256)
            *(float4*)(W + t * 4) = *(const float4*)(Wg + t * 4);
    }

    // fused deterministic aggregation: warp per row, original edge order, + h[n]
    {
        int wrp = tid >> 5, lane = tid & 31, cagg = lane * 4;
        #pragma unroll 1
        for (int rr = 0; rr < 8; rr++) {
            int row = wrp * 8 + rr;
            int n = row0 + row;
            float a0 = 0.f, a1 = 0.f, a2 = 0.f, a3 = 0.f;
            if (n < N_NODES) {
                int s = g_csr[n], e = g_csr[n + 1];
                int i = s;
                for (; i + 2 <= e; i += 2) {
                    int s0 = g_src_sorted[i], s1 = g_src_sorted[i + 1];
                    float4 v0 = *(const float4*)(g_h + (size_t)s0 * DIM + cagg);
                    float4 v1 = *(const float4*)(g_h + (size_t)s1 * DIM + cagg);
                    a0 = __fadd_rn(a0, v0.x); a1 = __fadd_rn(a1, v0.y);
                    a2 = __fadd_rn(a2, v0.z); a3 = __fadd_rn(a3, v0.w);
                    a0 = __fadd_rn(a0, v1.x); a1 = __fadd_rn(a1, v1.y);
                    a2 = __fadd_rn(a2, v1.z); a3 = __fadd_rn(a3, v1.w);
                }
                if (i < e) {
                    int s0 = g_src_sorted[i];
                    float4 v0 = *(const float4*)(g_h + (size_t)s0 * DIM + cagg);
                    a0 = __fadd_rn(a0, v0.x); a1 = __fadd_rn(a1, v0.y);
                    a2 = __fadd_rn(a2, v0.z); a3 = __fadd_rn(a3, v0.w);
                }
                float4 hv = *(const float4*)(g_h + (size_t)n * DIM + cagg);
                a0 = __fadd_rn(a0, hv.x); a1 = __fadd_rn(a1, hv.y);
                a2 = __fadd_rn(a2, hv.z); a3 = __fadd_rn(a3, hv.w);
            }
            float4 o = make_float4(a0, a1, a2, a3);
            *(float4*)(A + row * A_LD + cagg) = o;
        }
    }
    __syncthreads();

    int ty = tid >> 4, tx = tid & 15;
    int r0 = ty * 4, c0 = tx * 8;

    unsigned long long acc2[4][4];
    #pragma unroll
    for (int r = 0; r < 4; r++)
        #pragma unroll
        for (int j = 0; j < 4; j++) acc2[r][j] = 0ull;

    #pragma unroll 4
    for (int k = 0; k < DIM; k += 4) {
        float a[4][4];
        #pragma unroll
        for (int r = 0; r < 4; r++)
            *(float4*)&a[r][0] = *(const float4*)(A + (r0 + r) * A_LD + k);
        #pragma unroll
        for (int kk = 0; kk < 4; kk++) {
            ulonglong2 wA = *(const ulonglong2*)(W + (k + kk) * DIM + c0);
            ulonglong2 wB = *(const ulonglong2*)(W + (k + kk) * DIM + c0 + 4);
            #pragma unroll
            for (int r = 0; r < 4; r++) {
                unsigned long long a2 = pack2(a[r][kk]);
                acc2[r][0] = ffma2(a2, wA.x, acc2[r][0]);
                acc2[r][1] = ffma2(a2, wA.y, acc2[r][1]);
                acc2[r][2] = ffma2(a2, wB.x, acc2[r][2]);
                acc2[r][3] = ffma2(a2, wB.y, acc2[r][3]);
            }
        }
    }

    float tv[4][8];
    {
        const float* bp = b1g + layer * DIM;
        float bv[8];
        #pragma unroll
        for (int j = 0; j < 8; j++) bv[j] = bp[c0 + j];
        #pragma unroll
        for (int r = 0; r < 4; r++) {
            float o[8];
            #pragma unroll
            for (int j = 0; j < 4; j++) unpack2(acc2[r][j], o[2 * j], o[2 * j + 1]);
            #pragma unroll
            for (int j = 0; j < 8; j++) tv[r][j] = fmaxf(__fadd_rn(o[j], bv[j]), 0.f);
        }
    }
    __syncthreads();

    #pragma unroll
    for (int r = 0; r < 4; r++) {
        *(float4*)(A + (r0 + r) * A_LD + c0)     = *(float4*)&tv[r][0];
        *(float4*)(A + (r0 + r) * A_LD + c0 + 4) = *(float4*)&tv[r][4];
    }
    {
        const float* Wg = W2g + (size_t)layer * DIM * DIM;
        for (int t = tid; t < 4096; t += 256)
            *(float4*)(W + t * 4) = *(const float4*)(Wg + t * 4);
    }
    __syncthreads();

    #pragma unroll
    for (int r = 0; r < 4; r++)
        #pragma unroll
        for (int j = 0; j < 4; j++) acc2[r][j] = 0ull;

    #pragma unroll 4
    for (int k = 0; k < DIM; k += 4) {
        float a[4][4];
        #pragma unroll
        for (int r = 0; r < 4; r++)
            *(float4*)&a[r][0] = *(const float4*)(A + (r0 + r) * A_LD + k);
        #pragma unroll
        for (int kk = 0; kk < 4; kk++) {
            ulonglong2 wA = *(const ulonglong2*)(W + (k + kk) * DIM + c0);
            ulonglong2 wB = *(const ulonglong2*)(W + (k + kk) * DIM + c0 + 4);
            #pragma unroll
            for (int r = 0; r < 4; r++) {
                unsigned long long a2 = pack2(a[r][kk]);
                acc2[r][0] = ffma2(a2, wA.x, acc2[r][0]);
                acc2[r][1] = ffma2(a2, wA.y, acc2[r][1]);
                acc2[r][2] = ffma2(a2, wB.x, acc2[r][2]);
                acc2[r][3] = ffma2(a2, wB.y, acc2[r][3]);
            }
        }
    }

    float s[8], sq[8];
    #pragma unroll
    for (int j = 0; j < 8; j++) { s[j] = 0.f; sq[j] = 0.f; }
    {
        const float* bp = b2g + layer * DIM;
        float bv[8];
        #pragma unroll
        for (int j = 0; j < 8; j++) bv[j] = bp[c0 + j];
        #pragma unroll
        for (int r = 0; r < 4; r++) {
            if (row0 + r0 + r < N_NODES) {
                float o[8];
                #pragma unroll
                for (int j = 0; j < 4; j++) unpack2(acc2[r][j], o[2 * j], o[2 * j + 1]);
                #pragma unroll
                for (int j = 0; j < 8; j++) {
                    o[j] = fmaxf(__fadd_rn(o[j], bv[j]), 0.f);
                    s[j]  += o[j];
                    sq[j] = fmaf(o[j], o[j], sq[j]);
                }
                *(float4*)(g_h2 + (size_t)(row0 + r0 + r) * DIM + c0)     = *(float4*)&o[0];
                *(float4*)(g_h2 + (size_t)(row0 + r0 + r) * DIM + c0 + 4) = *(float4*)&o[4];
            }
        }
    }

    __syncthreads();
    float* red = W;
    #pragma unroll
    for (int j = 0; j < 8; j++) red[tid * 8 + j] = s[j];
    __syncthreads();
    if (tid < DIM) {
        int txc = tid >> 3, j = tid & 7;
        float ssum = 0.f;
        #pragma unroll
        for (int t = 0; t < 16; t++) ssum += red[((t << 4) + txc) * 8 + j];
        atomicAdd(&g_colsum[layer * DIM + tid], (double)ssum);
    }
    __syncthreads();
    #pragma unroll
    for (int j = 0; j < 8; j++) red[tid * 8 + j] = sq[j];
    __syncthreads();
    if (tid < DIM) {
        int txc = tid >> 3, j = tid & 7;
        float ssum = 0.f;
        #pragma unroll
        for (int t = 0; t < 16; t++) ssum += red[((t << 4) + txc) * 8 + j];
        atomicAdd(&g_colsumsq[layer * DIM + tid], (double)ssum);
    }
}

// BN apply (finalize folded in; reads g_h2, writes g_h + xs output) ----------------
__global__ void bn_apply_kernel(const float* __restrict__ gamma, const float* __restrict__ beta,
                                float* out, int layer) {
    __shared__ float smean[DIM], sinv[DIM];
    if (threadIdx.x < DIM) {
        int c = threadIdx.x;
        double m = g_colsum[layer * DIM + c] * (1.0 / (double)N_NODES);
        double q = g_colsumsq[layer * DIM + c] * (1.0 / (double)N_NODES);
        double var = q - m * m;
        float var32 = (float)var;
        smean[c] = (float)m;
        sinv[c]  = __fdiv_rn(1.0f, __fsqrt_rn(__fadd_rn(var32, 1e-5f)));
    }
    __syncthreads();

    int wid  = (blockIdx.x * blockDim.x + threadIdx.x) >> 5;
    if (wid >= N_NODES) return;
    int lane = threadIdx.x & 31;
    int c0 = lane * 4;
    size_t base = (size_t)wid * DIM + c0;
    float4 hv = *(const float4*)(g_h2 + base);
    float4 mn = *(const float4*)(smean + c0);
    float4 is = *(const float4*)(sinv  + c0);
    float4 ga = *(const float4*)(gamma + layer * DIM + c0);
    float4 be = *(const float4*)(beta  + layer * DIM + c0);
    float4 v;
    v.x = __fadd_rn(__fmul_rn(__fmul_rn(__fsub_rn(hv.x, mn.x), is.x), ga.x), be.x);
    v.y = __fadd_rn(__fmul_rn(__fmul_rn(__fsub_rn(hv.y, mn.y), is.y), ga.y), be.y);
    v.z = __fadd_rn(__fmul_rn(__fmul_rn(__fsub_rn(hv.z, mn.z), is.z), ga.z), be.z);
    v.w = __fadd_rn(__fmul_rn(__fmul_rn(__fsub_rn(hv.w, mn.w), is.w), ga.w), be.w);

    *(float4*)(g_h + base) = v;
    *(float4*)(out + XS_BASE + (size_t)wid * 384 + layer * DIM + c0) = v;
}

// ------------------------- residual VQ: thread/node, FFMA2 over code pairs -------
__global__ void __launch_bounds__(128) rvq_kernel(float* out, int layer) {
    __shared__ float scbT[NR * DIM * NC];   // [l][d][k]  24 KB
    __shared__ double dred[128];
    int tid = threadIdx.x;
    for (int i = tid; i < NR * NC * DIM; i += 128) {
        int l = i / (NC * DIM);
        int k = (i / DIM) % NC;
        int d = i % DIM;
        scbT[l * (DIM * NC) + d * NC + k] =
            g_cbn[(size_t)layer * NR * NC * DIM + i];
    }
    __syncthreads();

    int n = blockIdx.x * 128 + tid;
    float lsum[NR] = {0.f, 0.f, 0.f};

    if (n < N_NODES) {
        float r[DIM];
        #pragma unroll
        for (int d4 = 0; d4 < DIM; d4 += 4)
            *(float4*)(r + d4) = *(const float4*)(g_h + (size_t)n * DIM + d4);

        int bests[NR];
        #pragma unroll 1
        for (int l = 0; l < NR; l++) {
            float ss = 0.0f;
            #pragma unroll
            for (int d = 0; d < DIM; d++) ss = __fadd_rn(ss, __fmul_rn(r[d], r[d]));
            float sc = __fdiv_rn(1.0f, __fsqrt_rn(__fadd_rn(ss, 1e-12f)));

            const float* cT = scbT + l * (DIM * NC);
            unsigned long long acc2[NC / 2];
            #pragma unroll
            for (int k2 = 0; k2 < NC / 2; k2++) acc2[k2] = 0ull;
            #pragma unroll
            for (int d = 0; d < DIM; d++) {
                unsigned long long rn2 = pack2(__fmul_rn(r[d], sc));
                #pragma unroll
                for (int k2 = 0; k2 < NC / 2; k2++) {
                    unsigned long long w =
                        *(const unsigned long long*)(cT + d * NC + 2 * k2);
                    acc2[k2] = ffma2(rn2, w, acc2[k2]);
                }
            }
            float acc[NC];
            #pragma unroll
            for (int k2 = 0; k2 < NC / 2; k2++)
                unpack2(acc2[k2], acc[2 * k2], acc[2 * k2 + 1]);

            int best = 0; float bs = acc[0];
            #pragma unroll
            for (int k = 1; k < NC; k++)
                if (acc[k] > bs) { bs = acc[k]; best = k; }

            float ls = 0.0f;
            #pragma unroll
            for (int d = 0; d < DIM; d++) {
                float q = cT[d * NC + best];
                float diff = __fsub_rn(q, r[d]);
                ls = fmaf(diff, diff, ls);
                r[d] = __fsub_rn(r[d], q);
            }
            lsum[l] = ls;
            bests[l] = best;
        }
        #pragma unroll
        for (int l = 0; l < NR; l++)
            out[ID_BASE + (size_t)n * 9 + layer * 3 + l] = (float)bests[l];
    }

    #pragma unroll 1
    for (int l = 0; l < NR; l++) {
        dred[tid] = (double)lsum[l];
        __syncthreads();
        for (int off = 64; off; off >>= 1) {
            if (tid < off) dred[tid] += dred[tid + off];
            __syncthreads();
        }
        if (tid == 0) atomicAdd(&g_loss[layer * 3 + l], dred[0]);
        __syncthreads();
    }
}

// ------------------------- pool: one block per graph, deterministic ---------------
__global__ void pool_kernel(const int* __restrict__ batch, float* out) {
    int g = blockIdx.x;
    int c = threadIdx.x;   // 384 threads, one column each
    __shared__ int seg[2];
    if (c < 2) {
        int target = g + c;
        int lo = 0, hi = N_NODES;
        while (lo < hi) {
            int mid = (lo + hi) >> 1;
            if (__ldg(batch + mid) < target) lo = mid + 1; else hi = mid;
        }
        seg[c] = lo;
    }
    __syncthreads();
    int s = seg[0], e = seg[1];
    float acc = 0.0f;
    for (int n = s; n < e; n++)
        acc = __fadd_rn(acc, out[XS_BASE + (size_t)n * 384 + c]);
    out[(size_t)g * 384 + c] = acc;
}

__global__ void loss_final_kernel(float* out) {
    if (threadIdx.x == 0) {
        float loss = 0.0f;
        for (int i = 0; i < NL * NR; i++) {
            float m = (float)(g_loss[i] * (1.0 / 12800000.0));
            loss = __fadd_rn(loss, __fmul_rn(0.25f, m));
        }
        out[LOSS_IDX] = loss;
    }
}

// ------------------------- launch -------------------------
extern "C" void kernel_launch(void* const* d_in, const int* in_sizes, int n_in,
                              void* d_out, int out_size) {
    const float* x      = (const float*)d_in[0];
    const int*   ei     = (const int*)d_in[1];
    const int*   batch  = (const int*)d_in[2];
    const float* W1     = (const float*)d_in[3];
    const float* b1     = (const float*)d_in[4];
    const float* W2     = (const float*)d_in[5];
    const float* b2     = (const float*)d_in[6];
    const float* gamma  = (const float*)d_in[7];
    const float* beta   = (const float*)d_in[8];
    const float* cb     = (const float*)d_in[9];
    float* out = (float*)d_out;

    cudaFuncSetAttribute(mlp_kernel, cudaFuncAttributeMaxDynamicSharedMemorySize, MLP_SMEM);

    init_kernel<<<(N_NODES + 255) / 256, 256>>>();
    cbnorm_kernel<<<1, 256>>>(cb);
    copy_x_kernel<<<(N_NODES * (DIM / 4) + 255) / 256, 256>>>(x);

    count_kernel<<<(N_EDGES + 255) / 256, 256>>>(ei);
    scan_kernel<<<1, 1024>>>();
    place_kernel<<<(N_EDGES + 255) / 256, 256>>>(ei);
    rank_kernel<<<(N_NODES * 32 + 255) / 256, 256>>>(ei);

    const int mlp_blocks  = (N_NODES + BM - 1) / BM;
    const int node_blocks = (N_NODES * 32 + 255) / 256;
    const int rvq_blocks  = (N_NODES + 127) / 128;

    for (int i = 0; i < NL; i++) {
        mlp_kernel<<<mlp_blocks, 256, MLP_SMEM>>>(W1, b1, W2, b2, i);
        bn_apply_kernel<<<node_blocks, 256>>>(gamma, beta, out, i);
        rvq_kernel<<<rvq_blocks, 128>>>(out, i);
    }
    pool_kernel<<<NG, 384>>>(batch, out);
    loss_final_kernel<<<1, 32>>>(out);
}

// round 7
// speedup vs baseline: 1.0617x; 1.0617x over previous
#include <cuda_runtime.h>
#include <cstdint>

#define N_NODES 100000
#define N_EDGES 1600000
#define DIM     128
#define NL      3
#define NR      3
#define NC      16
#define NG      512

#define XPOOL_ELEMS ((size_t)NG * 384)
#define XS_BASE     (XPOOL_ELEMS)
#define LOSS_IDX    (XS_BASE + (size_t)N_NODES * 384)
#define ID_BASE     (LOSS_IDX + 1)

// ------------------------- device scratch -------------------------
__device__ float  g_h[(size_t)N_NODES * DIM];    // node features (post-BN / input)
__device__ float  g_agg[(size_t)N_NODES * DIM];  // aggregated features
__device__ float  g_cbn[NL * NR * NC * DIM];
__device__ double g_colsum[NL * DIM];
__device__ double g_colsumsq[NL * DIM];
__device__ double g_loss[NL * NR];
__device__ int    g_deg[N_NODES];
__device__ int    g_cursor[N_NODES];
__device__ int    g_csr[N_NODES + 1];
__device__ int    g_eid[N_EDGES];
__device__ int    g_src_sorted[N_EDGES];

// ------------------------- f32x2 packed math (per-lane IEEE fp32 fma) ----------
__device__ __forceinline__ unsigned long long pack2(float x) {
    unsigned long long r;
    asm("mov.b64 %0, {%1, %1};" : "=l"(r) : "f"(x));
    return r;
}
__device__ __forceinline__ unsigned long long ffma2(unsigned long long a,
                                                    unsigned long long b,
                                                    unsigned long long c) {
    unsigned long long d;
    asm("fma.rn.f32x2 %0, %1, %2, %3;" : "=l"(d) : "l"(a), "l"(b), "l"(c));
    return d;
}
__device__ __forceinline__ void unpack2(unsigned long long v, float& lo, float& hi) {
    asm("mov.b64 {%0, %1}, %2;" : "=f"(lo), "=f"(hi) : "l"(v));
}
__device__ __forceinline__ void red_add_v4(float* a, float4 v) {
    asm volatile("red.global.add.v4.f32 [%0], {%1,%2,%3,%4};"
                 :: "l"(a), "f"(v.x), "f"(v.y), "f"(v.z), "f"(v.w) : "memory");
}

// ------------------------- init -------------------------
// grid must cover max(XPOOL_ELEMS, N_NODES) threads!
__global__ void init_kernel(float* out) {
    int i = blockIdx.x * blockDim.x + threadIdx.x;
    if (i < (int)XPOOL_ELEMS) out[i] = 0.0f;
    if (i < N_NODES) { g_deg[i] = 0; g_cursor[i] = 0; }
    if (i < NL * DIM) { g_colsum[i] = 0.0; g_colsumsq[i] = 0.0; }
    if (i < NL * NR) g_loss[i] = 0.0;
}

// codebook normalization: one thread per code, sequential fp32
__global__ void cbnorm_kernel(const float* __restrict__ cb) {
    int c = blockIdx.x * blockDim.x + threadIdx.x;
    if (c >= NL * NR * NC) return;
    const float* src = cb + (size_t)c * DIM;
    float ss = 0.0f;
    for (int d = 0; d < DIM; d++) ss = __fadd_rn(ss, __fmul_rn(src[d], src[d]));
    float sc = __fdiv_rn(1.0f, __fsqrt_rn(__fadd_rn(ss, 1e-12f)));
    for (int d = 0; d < DIM; d++) g_cbn[(size_t)c * DIM + d] = __fmul_rn(src[d], sc);
}

__global__ void copy_x_kernel(const float* __restrict__ x) {
    int i = blockIdx.x * blockDim.x + threadIdx.x;
    if (i < N_NODES * (DIM / 4))
        *(float4*)(g_h + (size_t)i * 4) = *(const float4*)(x + (size_t)i * 4);
}

// ------------------------- CSR build (stable by edge id) -------------------------
__global__ void count_kernel(const int* __restrict__ ei) {
    int e = blockIdx.x * blockDim.x + threadIdx.x;
    if (e < N_EDGES) atomicAdd(&g_deg[__ldg(ei + N_EDGES + e)], 1);
}

__global__ void scan_kernel() {   // single block, 1024 threads
    __shared__ int wsum[32];
    __shared__ int carry;
    int tid = threadIdx.x, lane = tid & 31, wid = tid >> 5;
    if (tid == 0) carry = 0;
    __syncthreads();
    for (int base = 0; base < N_NODES; base += 1024) {
        int i = base + tid;
        int v = (i < N_NODES) ? g_deg[i] : 0;
        int incl = v;
        #pragma unroll
        for (int off = 1; off < 32; off <<= 1) {
            int t = __shfl_up_sync(0xffffffffu, incl, off);
            if (lane >= off) incl += t;
        }
        if (lane == 31) wsum[wid] = incl;
        __syncthreads();
        if (wid == 0) {
            int w = wsum[lane];
            #pragma unroll
            for (int off = 1; off < 32; off <<= 1) {
                int t = __shfl_up_sync(0xffffffffu, w, off);
                if (lane >= off) w += t;
            }
            wsum[lane] = w;
        }
        __syncthreads();
        int pre = (wid > 0) ? wsum[wid - 1] : 0;
        int excl = carry + pre + incl - v;
        if (i < N_NODES) g_csr[i] = excl;
        int btotal = wsum[31];
        __syncthreads();
        if (tid == 0) carry += btotal;
        __syncthreads();
    }
    if (threadIdx.x == 0) g_csr[N_NODES] = carry;
}

__global__ void place_kernel(const int* __restrict__ ei) {
    int e = blockIdx.x * blockDim.x + threadIdx.x;
    if (e >= N_EDGES) return;
    int dst = __ldg(ei + N_EDGES + e);
    int pos = g_csr[dst] + atomicAdd(&g_cursor[dst], 1);
    g_eid[pos] = e;
}

// warp-per-node rank-by-count: restores original edge order (eids distinct)
__global__ void rank_kernel(const int* __restrict__ ei) {
    int wid  = (blockIdx.x * blockDim.x + threadIdx.x) >> 5;
    if (wid >= N_NODES) return;
    int lane = threadIdx.x & 31;
    int s = g_csr[wid], e = g_csr[wid + 1], deg = e - s;
    for (int i = lane; i < deg; i += 32) {
        int my = g_eid[s + i];
        int rank = 0;
        for (int j = 0; j < deg; j++) rank += (g_eid[s + j] < my) ? 1 : 0;
        g_src_sorted[s + rank] = __ldg(ei + my);
    }
}

// ------------------------- deterministic aggregation (edge order) ----------------
__global__ void agg_kernel() {
    int wid  = (blockIdx.x * blockDim.x + threadIdx.x) >> 5;
    if (wid >= N_NODES) return;
    int lane = threadIdx.x & 31;
    int c0 = lane * 4;
    int s = g_csr[wid], e = g_csr[wid + 1];
    float a0 = 0.f, a1 = 0.f, a2 = 0.f, a3 = 0.f;
    int i = s;
    for (; i + 2 <= e; i += 2) {
        int s0 = g_src_sorted[i], s1 = g_src_sorted[i + 1];
        float4 v0 = *(const float4*)(g_h + (size_t)s0 * DIM + c0);
        float4 v1 = *(const float4*)(g_h + (size_t)s1 * DIM + c0);
        a0 = __fadd_rn(a0, v0.x); a1 = __fadd_rn(a1, v0.y);
        a2 = __fadd_rn(a2, v0.z); a3 = __fadd_rn(a3, v0.w);
        a0 = __fadd_rn(a0, v1.x); a1 = __fadd_rn(a1, v1.y);
        a2 = __fadd_rn(a2, v1.z); a3 = __fadd_rn(a3, v1.w);
    }
    if (i < e) {
        int s0 = g_src_sorted[i];
        float4 v0 = *(const float4*)(g_h + (size_t)s0 * DIM + c0);
        a0 = __fadd_rn(a0, v0.x); a1 = __fadd_rn(a1, v0.y);
        a2 = __fadd_rn(a2, v0.z); a3 = __fadd_rn(a3, v0.w);
    }
    float4 hv = *(const float4*)(g_h + (size_t)wid * DIM + c0);
    float4 o;
    o.x = __fadd_rn(a0, hv.x); o.y = __fadd_rn(a1, hv.y);
    o.z = __fadd_rn(a2, hv.z); o.w = __fadd_rn(a3, hv.w);
    *(float4*)(g_agg + (size_t)wid * DIM + c0) = o;
}

// ------------------------- MLP + BN stats (FFMA2); g_agg -> g_h ------------------
#define BM 64
#define A_LD 132
#define MLP_SMEM ((BM * A_LD + DIM * DIM) * 4)

__global__ void mlp_kernel(const float* __restrict__ W1g, const float* __restrict__ b1g,
                           const float* __restrict__ W2g, const float* __restrict__ b2g,
                           int layer) {
    extern __shared__ float sm[];
    float* A = sm;
    float* W = sm + BM * A_LD;

    int tid  = threadIdx.x;
    int row0 = blockIdx.x * BM;

    for (int t = tid; t < BM * 32; t += 256) {
        int r = t >> 5, c4 = (t & 31) << 2;
        float4 v = make_float4(0.f, 0.f, 0.f, 0.f);
        if (row0 + r < N_NODES) v = *(const float4*)(g_agg + (size_t)(row0 + r) * DIM + c4);
        *(float4*)(A + r * A_LD + c4) = v;
    }
    {
        const float* Wg = W1g + (size_t)layer * DIM * DIM;
        for (int t = tid; t < 4096; t += 256)
            *(float4*)(W + t * 4) = *(const float4*)(Wg + t * 4);
    }
    __syncthreads();

    int ty = tid >> 4, tx = tid & 15;
    int r0 = ty * 4, c0 = tx * 8;

    unsigned long long acc2[4][4];
    #pragma unroll
    for (int r = 0; r < 4; r++)
        #pragma unroll
        for (int j = 0; j < 4; j++) acc2[r][j] = 0ull;

    #pragma unroll 4
    for (int k = 0; k < DIM; k += 4) {
        float a[4][4];
        #pragma unroll
        for (int r = 0; r < 4; r++)
            *(float4*)&a[r][0] = *(const float4*)(A + (r0 + r) * A_LD + k);
        #pragma unroll
        for (int kk = 0; kk < 4; kk++) {
            ulonglong2 wA = *(const ulonglong2*)(W + (k + kk) * DIM + c0);
            ulonglong2 wB = *(const ulonglong2*)(W + (k + kk) * DIM + c0 + 4);
            #pragma unroll
            for (int r = 0; r < 4; r++) {
                unsigned long long a2 = pack2(a[r][kk]);
                acc2[r][0] = ffma2(a2, wA.x, acc2[r][0]);
                acc2[r][1] = ffma2(a2, wA.y, acc2[r][1]);
                acc2[r][2] = ffma2(a2, wB.x, acc2[r][2]);
                acc2[r][3] = ffma2(a2, wB.y, acc2[r][3]);
            }
        }
    }

    float tv[4][8];
    {
        const float* bp = b1g + layer * DIM;
        float bv[8];
        #pragma unroll
        for (int j = 0; j < 8; j++) bv[j] = bp[c0 + j];
        #pragma unroll
        for (int r = 0; r < 4; r++) {
            float o[8];
            #pragma unroll
            for (int j = 0; j < 4; j++) unpack2(acc2[r][j], o[2 * j], o[2 * j + 1]);
            #pragma unroll
            for (int j = 0; j < 8; j++) tv[r][j] = fmaxf(__fadd_rn(o[j], bv[j]), 0.f);
        }
    }
    __syncthreads();

    #pragma unroll
    for (int r = 0; r < 4; r++) {
        *(float4*)(A + (r0 + r) * A_LD + c0)     = *(float4*)&tv[r][0];
        *(float4*)(A + (r0 + r) * A_LD + c0 + 4) = *(float4*)&tv[r][4];
    }
    {
        const float* Wg = W2g + (size_t)layer * DIM * DIM;
        for (int t = tid; t < 4096; t += 256)
            *(float4*)(W + t * 4) = *(const float4*)(Wg + t * 4);
    }
    __syncthreads();

    #pragma unroll
    for (int r = 0; r < 4; r++)
        #pragma unroll
        for (int j = 0; j < 4; j++) acc2[r][j] = 0ull;

    #pragma unroll 4
    for (int k = 0; k < DIM; k += 4) {
        float a[4][4];
        #pragma unroll
        for (int r = 0; r < 4; r++)
            *(float4*)&a[r][0] = *(const float4*)(A + (r0 + r) * A_LD + k);
        #pragma unroll
        for (int kk = 0; kk < 4; kk++) {
            ulonglong2 wA = *(const ulonglong2*)(W + (k + kk) * DIM + c0);
            ulonglong2 wB = *(const ulonglong2*)(W + (k + kk) * DIM + c0 + 4);
            #pragma unroll
            for (int r = 0; r < 4; r++) {
                unsigned long long a2 = pack2(a[r][kk]);
                acc2[r][0] = ffma2(a2, wA.x, acc2[r][0]);
                acc2[r][1] = ffma2(a2, wA.y, acc2[r][1]);
                acc2[r][2] = ffma2(a2, wB.x, acc2[r][2]);
                acc2[r][3] = ffma2(a2, wB.y, acc2[r][3]);
            }
        }
    }

    float s[8], sq[8];
    #pragma unroll
    for (int j = 0; j < 8; j++) { s[j] = 0.f; sq[j] = 0.f; }
    {
        const float* bp = b2g + layer * DIM;
        float bv[8];
        #pragma unroll
        for (int j = 0; j < 8; j++) bv[j] = bp[c0 + j];
        #pragma unroll
        for (int r = 0; r < 4; r++) {
            if (row0 + r0 + r < N_NODES) {
                float o[8];
                #pragma unroll
                for (int j = 0; j < 4; j++) unpack2(acc2[r][j], o[2 * j], o[2 * j + 1]);
                #pragma unroll
                for (int j = 0; j < 8; j++) {
                    o[j] = fmaxf(__fadd_rn(o[j], bv[j]), 0.f);
                    s[j]  += o[j];
                    sq[j] = fmaf(o[j], o[j], sq[j]);
                }
                *(float4*)(g_h + (size_t)(row0 + r0 + r) * DIM + c0)     = *(float4*)&o[0];
                *(float4*)(g_h + (size_t)(row0 + r0 + r) * DIM + c0 + 4) = *(float4*)&o[4];
            }
        }
    }

    __syncthreads();
    float* red = W;
    #pragma unroll
    for (int j = 0; j < 8; j++) red[tid * 8 + j] = s[j];
    __syncthreads();
    if (tid < DIM) {
        int txc = tid >> 3, j = tid & 7;
        float ssum = 0.f;
        #pragma unroll
        for (int t = 0; t < 16; t++) ssum += red[((t << 4) + txc) * 8 + j];
        atomicAdd(&g_colsum[layer * DIM + tid], (double)ssum);
    }
    __syncthreads();
    #pragma unroll
    for (int j = 0; j < 8; j++) red[tid * 8 + j] = sq[j];
    __syncthreads();
    if (tid < DIM) {
        int txc = tid >> 3, j = tid & 7;
        float ssum = 0.f;
        #pragma unroll
        for (int t = 0; t < 16; t++) ssum += red[((t << 4) + txc) * 8 + j];
        atomicAdd(&g_colsumsq[layer * DIM + tid], (double)ssum);
    }
}

// BN apply (finalize folded) + xs output + xpool atomic accumulation ---------------
__global__ void bn_apply_kernel(const float* __restrict__ gamma, const float* __restrict__ beta,
                                const int* __restrict__ batch, float* out, int layer) {
    __shared__ float smean[DIM], sinv[DIM];
    if (threadIdx.x < DIM) {
        int c = threadIdx.x;
        double m = g_colsum[layer * DIM + c] * (1.0 / (double)N_NODES);
        double q = g_colsumsq[layer * DIM + c] * (1.0 / (double)N_NODES);
        double var = q - m * m;
        float var32 = (float)var;
        smean[c] = (float)m;
        sinv[c]  = __fdiv_rn(1.0f, __fsqrt_rn(__fadd_rn(var32, 1e-5f)));
    }
    __syncthreads();

    int wid  = (blockIdx.x * blockDim.x + threadIdx.x) >> 5;
    if (wid >= N_NODES) return;
    int lane = threadIdx.x & 31;
    int c0 = lane * 4;
    size_t base = (size_t)wid * DIM + c0;
    float4 hv = *(const float4*)(g_h + base);
    float4 mn = *(const float4*)(smean + c0);
    float4 is = *(const float4*)(sinv  + c0);
    float4 ga = *(const float4*)(gamma + layer * DIM + c0);
    float4 be = *(const float4*)(beta  + layer * DIM + c0);
    float4 v;
    v.x = __fadd_rn(__fmul_rn(__fmul_rn(__fsub_rn(hv.x, mn.x), is.x), ga.x), be.x);
    v.y = __fadd_rn(__fmul_rn(__fmul_rn(__fsub_rn(hv.y, mn.y), is.y), ga.y), be.y);
    v.z = __fadd_rn(__fmul_rn(__fmul_rn(__fsub_rn(hv.z, mn.z), is.z), ga.z), be.z);
    v.w = __fadd_rn(__fmul_rn(__fmul_rn(__fsub_rn(hv.w, mn.w), is.w), ga.w), be.w);

    *(float4*)(g_h + base) = v;
    *(float4*)(out + XS_BASE + (size_t)wid * 384 + layer * DIM + c0) = v;
    int g = __ldg(batch + wid);
    red_add_v4(out + (size_t)g * 384 + layer * DIM + c0, v);
}

// ------------------------- residual VQ: thread/node, FFMA2 over code pairs -------
__global__ void __launch_bounds__(128) rvq_kernel(float* out, int layer) {
    __shared__ float scbT[NR * DIM * NC];   // [l][d][k]  24 KB
    __shared__ double dred[128];
    int tid = threadIdx.x;
    for (int i = tid; i < NR * NC * DIM; i += 128) {
        int l = i / (NC * DIM);
        int k = (i / DIM) % NC;
        int d = i % DIM;
        scbT[l * (DIM * NC) + d * NC + k] =
            g_cbn[(size_t)layer * NR * NC * DIM + i];
    }
    __syncthreads();

    int n = blockIdx.x * 128 + tid;
    float lsum[NR] = {0.f, 0.f, 0.f};

    if (n < N_NODES) {
        float r[DIM];
        #pragma unroll
        for (int d4 = 0; d4 < DIM; d4 += 4)
            *(float4*)(r + d4) = *(const float4*)(g_h + (size_t)n * DIM + d4);

        int bests[NR];
        #pragma unroll 1
        for (int l = 0; l < NR; l++) {
            float ss = 0.0f;
            #pragma unroll
            for (int d = 0; d < DIM; d++) ss = __fadd_rn(ss, __fmul_rn(r[d], r[d]));
            float sc = __fdiv_rn(1.0f, __fsqrt_rn(__fadd_rn(ss, 1e-12f)));

            const float* cT = scbT + l * (DIM * NC);
            unsigned long long acc2[NC / 2];
            #pragma unroll
            for (int k2 = 0; k2 < NC / 2; k2++) acc2[k2] = 0ull;
            #pragma unroll
            for (int d = 0; d < DIM; d++) {
                unsigned long long rn2 = pack2(__fmul_rn(r[d], sc));
                #pragma unroll
                for (int k2 = 0; k2 < NC / 2; k2++) {
                    unsigned long long w =
                        *(const unsigned long long*)(cT + d * NC + 2 * k2);
                    acc2[k2] = ffma2(rn2, w, acc2[k2]);
                }
            }
            float acc[NC];
            #pragma unroll
            for (int k2 = 0; k2 < NC / 2; k2++)
                unpack2(acc2[k2], acc[2 * k2], acc[2 * k2 + 1]);

            int best = 0; float bs = acc[0];
            #pragma unroll
            for (int k = 1; k < NC; k++)
                if (acc[k] > bs) { bs = acc[k]; best = k; }

            float ls = 0.0f;
            #pragma unroll
            for (int d = 0; d < DIM; d++) {
                float q = cT[d * NC + best];
                float diff = __fsub_rn(q, r[d]);
                ls = fmaf(diff, diff, ls);
                r[d] = __fsub_rn(r[d], q);
            }
            lsum[l] = ls;
            bests[l] = best;
        }
        #pragma unroll
        for (int l = 0; l < NR; l++)
            out[ID_BASE + (size_t)n * 9 + layer * 3 + l] = (float)bests[l];
    }

    #pragma unroll 1
    for (int l = 0; l < NR; l++) {
        dred[tid] = (double)lsum[l];
        __syncthreads();
        for (int off = 64; off; off >>= 1) {
            if (tid < off) dred[tid] += dred[tid + off];
            __syncthreads();
        }
        if (tid == 0) atomicAdd(&g_loss[layer * 3 + l], dred[0]);
        __syncthreads();
    }
}

__global__ void loss_final_kernel(float* out) {
    if (threadIdx.x == 0) {
        float loss = 0.0f;
        for (int i = 0; i < NL * NR; i++) {
            float m = (float)(g_loss[i] * (1.0 / 12800000.0));
            loss = __fadd_rn(loss, __fmul_rn(0.25f, m));
        }
        out[LOSS_IDX] = loss;
    }
}

// ------------------------- launch -------------------------
extern "C" void kernel_launch(void* const* d_in, const int* in_sizes, int n_in,
                              void* d_out, int out_size) {
    const float* x      = (const float*)d_in[0];
    const int*   ei     = (const int*)d_in[1];
    const int*   batch  = (const int*)d_in[2];
    const float* W1     = (const float*)d_in[3];
    const float* b1     = (const float*)d_in[4];
    const float* W2     = (const float*)d_in[5];
    const float* b2     = (const float*)d_in[6];
    const float* gamma  = (const float*)d_in[7];
    const float* beta   = (const float*)d_in[8];
    const float* cb     = (const float*)d_in[9];
    float* out = (float*)d_out;

    cudaFuncSetAttribute(mlp_kernel, cudaFuncAttributeMaxDynamicSharedMemorySize, MLP_SMEM);

    // grid covers max(XPOOL_ELEMS, N_NODES) = XPOOL_ELEMS
    init_kernel<<<(int)((XPOOL_ELEMS + 255) / 256), 256>>>(out);
    cbnorm_kernel<<<1, 256>>>(cb);
    copy_x_kernel<<<(N_NODES * (DIM / 4) + 255) / 256, 256>>>(x);

    count_kernel<<<(N_EDGES + 255) / 256, 256>>>(ei);
    scan_kernel<<<1, 1024>>>();
    place_kernel<<<(N_EDGES + 255) / 256, 256>>>(ei);
    rank_kernel<<<(N_NODES * 32 + 255) / 256, 256>>>(ei);

    const int agg_blocks  = (N_NODES * 32 + 255) / 256;
    const int mlp_blocks  = (N_NODES + BM - 1) / BM;
    const int node_blocks = (N_NODES * 32 + 255) / 256;
    const int rvq_blocks  = (N_NODES + 127) / 128;

    for (int i = 0; i < NL; i++) {
        agg_kernel<<<agg_blocks, 256>>>();
        mlp_kernel<<<mlp_blocks, 256, MLP_SMEM>>>(W1, b1, W2, b2, i);
        bn_apply_kernel<<<node_blocks, 256>>>(gamma, beta, batch, out, i);
        rvq_kernel<<<rvq_blocks, 128>>>(out, i);
    }
    loss_final_kernel<<<1, 32>>>(out);
}